// round 4
// baseline (speedup 1.0000x reference)
#include <cuda_runtime.h>
#include <cstdint>

// Problem constants (fixed by setup_inputs)
#define Nn     4
#define Cc     64
#define Hh     192
#define Ww     192
#define OUTC   3
#define Ss     4
#define SS2    16          // s*s
#define CK     576         // C*9
#define WCOLS  48          // s*s*outC
#define HIDDEN 256
#define M2     1728        // KS*KS*C*outC
#define TILE   16
#define HOUT   768
#define WOUT   768

// Dynamic conv weights, rearranged as g_w[k][sp*3+o], k = c*9 + i*3 + j
__device__ float g_w[CK * WCOLS];

// ---------------------------------------------------------------------------
// Stage 1: Pos2Weight MLP. grid = (16 subpixels, 8 m-chunks), block = 256.
// ---------------------------------------------------------------------------
__global__ void mlp_kernel(const float* __restrict__ W1, const float* __restrict__ b1,
                           const float* __restrict__ W2, const float* __restrict__ b2) {
    __shared__ float hidden[HIDDEN];
    const int sp = blockIdx.x;
    const int chunk = blockIdx.y;      // 8 chunks of 216 m-values (8*216 = 1728)
    const int tid = threadIdx.x;

    const float p0 = 0.25f;
    const float p1 = (float)(sp >> 2) * 0.25f;
    const float p2 = (float)(sp & 3) * 0.25f;

    float h = fmaf(p0, W1[tid], fmaf(p1, W1[256 + tid], fmaf(p2, W1[512 + tid], b1[tid])));
    hidden[tid] = fmaxf(h, 0.0f);
    __syncthreads();

    if (tid < 216) {
        const int m = chunk * 216 + tid;
        float sum = b2[m];
        #pragma unroll 8
        for (int j = 0; j < HIDDEN; ++j)
            sum = fmaf(hidden[j], W2[j * M2 + m], sum);
        const int k = m / 3;
        const int o = m - k * 3;
        g_w[k * WCOLS + sp * 3 + o] = sum;
    }
}

// ---------------------------------------------------------------------------
// f32x2 packed-math helpers (FFMA2 only reachable via PTX on sm_103a)
// ---------------------------------------------------------------------------
typedef unsigned long long u64;

__device__ __forceinline__ u64 f2dup(float v) {
    u64 r;
    asm("mov.b64 %0, {%1, %1};" : "=l"(r) : "f"(v));
    return r;
}
__device__ __forceinline__ u64 ffma2(u64 a, u64 b, u64 c) {
    u64 d;
    asm("fma.rn.f32x2 %0, %1, %2, %3;" : "=l"(d) : "l"(a), "l"(b), "l"(c));
    return d;
}
__device__ __forceinline__ void f2unpack(u64 v, float& lo, float& hi) {
    asm("mov.b64 {%0, %1}, %2;" : "=f"(lo), "=f"(hi) : "l"(v));
}

// ---------------------------------------------------------------------------
// Stage 2: fused dynamic conv + pixel shuffle.
// grid = (12, 12, 4) tiles; block = 256 threads.
// smem: weights 27648 f + input halo tile 64*18*18 = 20736 f  (193,536 B)
// Thread = 2x2 pixel block x 12 output columns (one si group), 24 f32x2 accs.
// ---------------------------------------------------------------------------
#define SW_FLOATS (CK * WCOLS)          // 27648
#define SX_FLOATS (Cc * 18 * 18)        // 20736
#define SMEM_BYTES ((SW_FLOATS + SX_FLOATS) * 4)

__global__ void __launch_bounds__(256, 1)
conv_kernel(const float* __restrict__ in, float* __restrict__ out) {
    extern __shared__ float smem[];
    float* sw = smem;                   // [576][48]
    float* sx = smem + SW_FLOATS;       // [64][18][18]
    float* stage = sx;                  // reused after compute: [12][16][64]

    const int tw = blockIdx.x, th = blockIdx.y, n = blockIdx.z;
    const int tid = threadIdx.x;

    // --- load weights (float4, coalesced) ---
    {
        const float4* gw4 = (const float4*)g_w;
        float4* sw4 = (float4*)sw;
        #pragma unroll 4
        for (int i = tid; i < SW_FLOATS / 4; i += 256) sw4[i] = gw4[i];
    }

    // --- load 18x18x64 halo tile with zero padding ---
    {
        const int gh0 = th * TILE - 1, gw0 = tw * TILE - 1;
        const float* inb = in + (size_t)n * Cc * Hh * Ww;
        for (int i = tid; i < SX_FLOATS; i += 256) {
            int c = i / 324, r = i - c * 324;
            int lh = r / 18, lw = r - lh * 18;
            int gh = gh0 + lh, gw = gw0 + lw;
            float v = 0.0f;
            if ((unsigned)gh < (unsigned)Hh && (unsigned)gw < (unsigned)Ww)
                v = inb[(c * Hh + gh) * Ww + gw];
            sx[i] = v;
        }
    }
    __syncthreads();

    const int og = tid & 3;             // output-column group: cols [og*12, og*12+12) -> si == og
    const int pg = tid >> 2;            // pixel group: 8x8 grid of 2x2 blocks
    const int h0l = (pg >> 3) * 2;      // local pixel row of 2x2 block
    const int w0l = (pg & 7) * 2;

    u64 acc[2][2][6];                   // [pixel r][pixel q][col pair]
    #pragma unroll
    for (int r = 0; r < 2; ++r)
        #pragma unroll
        for (int q = 0; q < 2; ++q)
            #pragma unroll
            for (int cp = 0; cp < 6; ++cp) acc[r][q][cp] = 0ull;

    #pragma unroll 1
    for (int c = 0; c < Cc; ++c) {
        // 4x4 input patch for this channel, broadcast-packed into f32x2 regs
        const float* xp = sx + c * 324 + h0l * 18 + w0l;
        u64 P[4][4];
        #pragma unroll
        for (int rr = 0; rr < 4; ++rr)
            #pragma unroll
            for (int qq = 0; qq < 4; ++qq)
                P[rr][qq] = f2dup(xp[rr * 18 + qq]);

        const float* wc = sw + c * 9 * WCOLS + og * 12;
        #pragma unroll
        for (int i = 0; i < 3; ++i) {
            #pragma unroll
            for (int j = 0; j < 3; ++j) {
                const ulonglong2* wv = (const ulonglong2*)(wc + (i * 3 + j) * WCOLS);
                ulonglong2 a = wv[0], b = wv[1], d = wv[2];
                u64 Wp[6] = {a.x, a.y, b.x, b.y, d.x, d.y};
                #pragma unroll
                for (int r = 0; r < 2; ++r)
                    #pragma unroll
                    for (int q = 0; q < 2; ++q)
                        #pragma unroll
                        for (int cp = 0; cp < 6; ++cp)
                            acc[r][q][cp] = ffma2(P[i + r][j + q], Wp[cp], acc[r][q][cp]);
            }
        }
    }

    __syncthreads();   // sx no longer needed; reuse as output staging

    // --- scatter accumulators into pixel-shuffled staging layout ---
    // stage[((o*4+si)*16 + hl)*64 + wl*4 + sj]
    #pragma unroll
    for (int r = 0; r < 2; ++r) {
        #pragma unroll
        for (int q = 0; q < 2; ++q) {
            const int hl = h0l + r, wl = w0l + q;
            #pragma unroll
            for (int cp = 0; cp < 6; ++cp) {
                float lo, hi;
                f2unpack(acc[r][q][cp], lo, hi);
                #pragma unroll
                for (int e = 0; e < 2; ++e) {
                    const int col = og * 12 + 2 * cp + e;   // = sp*3 + o
                    const int sp = col / 3;
                    const int o  = col - sp * 3;
                    const int si = sp >> 2;                 // == og
                    const int sj = sp & 3;
                    stage[(((o * 4 + si) * 16) + hl) * 64 + wl * 4 + sj] = (e == 0) ? lo : hi;
                }
            }
        }
    }
    __syncthreads();

    // --- coalesced float4 stores: each (o, hl, si) row is 64 contiguous floats ---
    {
        float* outb = out + (size_t)n * OUTC * HOUT * WOUT;
        const float4* st4 = (const float4*)stage;
        #pragma unroll
        for (int v = tid; v < (12 * 16 * 64) / 4; v += 256) {
            const int flat = v * 4;
            const int seg = flat >> 6;          // (o*4+si)*16 + hl
            const int cc = flat & 63;
            const int o = seg >> 6;
            const int rem = seg & 63;
            const int si = rem >> 4;
            const int hl = rem & 15;
            const int gh = (th * TILE + hl) * Ss + si;
            const int gw = tw * 64 + cc;
            *(float4*)(outb + ((size_t)o * HOUT + gh) * WOUT + gw) = st4[v];
        }
    }
}

// ---------------------------------------------------------------------------
extern "C" void kernel_launch(void* const* d_in, const int* in_sizes, int n_in,
                              void* d_out, int out_size) {
    const float* x  = (const float*)d_in[0];
    const float* W1 = (const float*)d_in[1];
    const float* b1 = (const float*)d_in[2];
    const float* W2 = (const float*)d_in[3];
    const float* b2 = (const float*)d_in[4];
    float* out = (float*)d_out;

    mlp_kernel<<<dim3(SS2, 8), 256>>>(W1, b1, W2, b2);

    cudaFuncSetAttribute(conv_kernel, cudaFuncAttributeMaxDynamicSharedMemorySize, SMEM_BYTES);
    conv_kernel<<<dim3(Ww / TILE, Hh / TILE, Nn), 256, SMEM_BYTES>>>(x, out);
}

// round 5
// speedup vs baseline: 1.0015x; 1.0015x over previous
#include <cuda_runtime.h>
#include <cstdint>

// Problem constants (fixed by setup_inputs)
#define Nn     4
#define Cc     64
#define Hh     192
#define Ww     192
#define OUTC   3
#define Ss     4
#define SS2    16          // s*s
#define CK     576         // C*9
#define WCOLS  48          // s*s*outC
#define HIDDEN 256
#define M2     1728        // KS*KS*C*outC
#define TILE   16
#define HOUT   768
#define WOUT   768

// Dynamic conv weights, rearranged as g_w[k][sp*3+o], k = c*9 + i*3 + j
__device__ float g_w[CK * WCOLS];

// ---------------------------------------------------------------------------
// Stage 1: Pos2Weight MLP. grid = (16 subpixels, 8 m-chunks), block = 256.
// ---------------------------------------------------------------------------
__global__ void mlp_kernel(const float* __restrict__ W1, const float* __restrict__ b1,
                           const float* __restrict__ W2, const float* __restrict__ b2) {
    __shared__ float hidden[HIDDEN];
    const int sp = blockIdx.x;
    const int chunk = blockIdx.y;      // 8 chunks of 216 m-values (8*216 = 1728)
    const int tid = threadIdx.x;

    const float p0 = 0.25f;
    const float p1 = (float)(sp >> 2) * 0.25f;
    const float p2 = (float)(sp & 3) * 0.25f;

    float h = fmaf(p0, W1[tid], fmaf(p1, W1[256 + tid], fmaf(p2, W1[512 + tid], b1[tid])));
    hidden[tid] = fmaxf(h, 0.0f);
    __syncthreads();

    if (tid < 216) {
        const int m = chunk * 216 + tid;
        float sum = b2[m];
        #pragma unroll 8
        for (int j = 0; j < HIDDEN; ++j)
            sum = fmaf(hidden[j], W2[j * M2 + m], sum);
        const int k = m / 3;
        const int o = m - k * 3;
        g_w[k * WCOLS + sp * 3 + o] = sum;
    }
}

// ---------------------------------------------------------------------------
// f32x2 packed-math helpers (FFMA2 only reachable via PTX on sm_103a)
// ---------------------------------------------------------------------------
typedef unsigned long long u64;

__device__ __forceinline__ u64 f2dup(float v) {
    u64 r;
    asm("mov.b64 %0, {%1, %1};" : "=l"(r) : "f"(v));
    return r;
}
__device__ __forceinline__ u64 ffma2(u64 a, u64 b, u64 c) {
    u64 d;
    asm("fma.rn.f32x2 %0, %1, %2, %3;" : "=l"(d) : "l"(a), "l"(b), "l"(c));
    return d;
}
__device__ __forceinline__ void f2unpack(u64 v, float& lo, float& hi) {
    asm("mov.b64 {%0, %1}, %2;" : "=f"(lo), "=f"(hi) : "l"(v));
}

// ---------------------------------------------------------------------------
// Stage 2: fused dynamic conv + pixel shuffle.
// grid = (12, 12, 4) tiles; block = 256 threads.
// smem: weights 27648 f + input halo tile 64*18*18 = 20736 f  (193,536 B)
// Thread = 2x2 pixel block x 12 output columns (one si group), 24 f32x2 accs.
// ---------------------------------------------------------------------------
#define SW_FLOATS (CK * WCOLS)          // 27648
#define SX_FLOATS (Cc * 18 * 18)        // 20736
#define SMEM_BYTES ((SW_FLOATS + SX_FLOATS) * 4)

__global__ void __launch_bounds__(256, 1)
conv_kernel(const float* __restrict__ in, float* __restrict__ out) {
    extern __shared__ float smem[];
    float* sw = smem;                   // [576][48]
    float* sx = smem + SW_FLOATS;       // [64][18][18]
    float* stage = sx;                  // reused after compute: [12][16][64]

    const int tw = blockIdx.x, th = blockIdx.y, n = blockIdx.z;
    const int tid = threadIdx.x;

    // --- load weights (float4, coalesced) ---
    {
        const float4* gw4 = (const float4*)g_w;
        float4* sw4 = (float4*)sw;
        #pragma unroll 4
        for (int i = tid; i < SW_FLOATS / 4; i += 256) sw4[i] = gw4[i];
    }

    // --- load 18x18x64 halo tile with zero padding ---
    {
        const int gh0 = th * TILE - 1, gw0 = tw * TILE - 1;
        const float* inb = in + (size_t)n * Cc * Hh * Ww;
        for (int i = tid; i < SX_FLOATS; i += 256) {
            int c = i / 324, r = i - c * 324;
            int lh = r / 18, lw = r - lh * 18;
            int gh = gh0 + lh, gw = gw0 + lw;
            float v = 0.0f;
            if ((unsigned)gh < (unsigned)Hh && (unsigned)gw < (unsigned)Ww)
                v = inb[(c * Hh + gh) * Ww + gw];
            sx[i] = v;
        }
    }
    __syncthreads();

    const int og = tid & 3;             // output-column group: cols [og*12, og*12+12) -> si == og
    const int pg = tid >> 2;            // pixel group: 8x8 grid of 2x2 blocks
    const int h0l = (pg >> 3) * 2;      // local pixel row of 2x2 block
    const int w0l = (pg & 7) * 2;

    u64 acc[2][2][6];                   // [pixel r][pixel q][col pair]
    #pragma unroll
    for (int r = 0; r < 2; ++r)
        #pragma unroll
        for (int q = 0; q < 2; ++q)
            #pragma unroll
            for (int cp = 0; cp < 6; ++cp) acc[r][q][cp] = 0ull;

    #pragma unroll 1
    for (int c = 0; c < Cc; ++c) {
        // 4x4 input patch for this channel, broadcast-packed into f32x2 regs
        const float* xp = sx + c * 324 + h0l * 18 + w0l;
        u64 P[4][4];
        #pragma unroll
        for (int rr = 0; rr < 4; ++rr)
            #pragma unroll
            for (int qq = 0; qq < 4; ++qq)
                P[rr][qq] = f2dup(xp[rr * 18 + qq]);

        const float* wc = sw + c * 9 * WCOLS + og * 12;
        #pragma unroll
        for (int i = 0; i < 3; ++i) {
            #pragma unroll
            for (int j = 0; j < 3; ++j) {
                const ulonglong2* wv = (const ulonglong2*)(wc + (i * 3 + j) * WCOLS);
                ulonglong2 a = wv[0], b = wv[1], d = wv[2];
                u64 Wp[6] = {a.x, a.y, b.x, b.y, d.x, d.y};
                #pragma unroll
                for (int r = 0; r < 2; ++r)
                    #pragma unroll
                    for (int q = 0; q < 2; ++q)
                        #pragma unroll
                        for (int cp = 0; cp < 6; ++cp)
                            acc[r][q][cp] = ffma2(P[i + r][j + q], Wp[cp], acc[r][q][cp]);
            }
        }
    }

    __syncthreads();   // sx no longer needed; reuse as output staging

    // --- scatter accumulators into pixel-shuffled staging layout ---
    // stage[((o*4+si)*16 + hl)*64 + wl*4 + sj]
    #pragma unroll
    for (int r = 0; r < 2; ++r) {
        #pragma unroll
        for (int q = 0; q < 2; ++q) {
            const int hl = h0l + r, wl = w0l + q;
            #pragma unroll
            for (int cp = 0; cp < 6; ++cp) {
                float lo, hi;
                f2unpack(acc[r][q][cp], lo, hi);
                #pragma unroll
                for (int e = 0; e < 2; ++e) {
                    const int col = og * 12 + 2 * cp + e;   // = sp*3 + o
                    const int sp = col / 3;
                    const int o  = col - sp * 3;
                    const int si = sp >> 2;                 // == og
                    const int sj = sp & 3;
                    stage[(((o * 4 + si) * 16) + hl) * 64 + wl * 4 + sj] = (e == 0) ? lo : hi;
                }
            }
        }
    }
    __syncthreads();

    // --- coalesced float4 stores: each (o, hl, si) row is 64 contiguous floats ---
    {
        float* outb = out + (size_t)n * OUTC * HOUT * WOUT;
        const float4* st4 = (const float4*)stage;
        #pragma unroll
        for (int v = tid; v < (12 * 16 * 64) / 4; v += 256) {
            const int flat = v * 4;
            const int seg = flat >> 6;          // (o*4+si)*16 + hl
            const int cc = flat & 63;
            const int o = seg >> 6;
            const int rem = seg & 63;
            const int si = rem >> 4;
            const int hl = rem & 15;
            const int gh = (th * TILE + hl) * Ss + si;
            const int gw = tw * 64 + cc;
            *(float4*)(outb + ((size_t)o * HOUT + gh) * WOUT + gw) = st4[v];
        }
    }
}

// ---------------------------------------------------------------------------
extern "C" void kernel_launch(void* const* d_in, const int* in_sizes, int n_in,
                              void* d_out, int out_size) {
    const float* x  = (const float*)d_in[0];
    const float* W1 = (const float*)d_in[1];
    const float* b1 = (const float*)d_in[2];
    const float* W2 = (const float*)d_in[3];
    const float* b2 = (const float*)d_in[4];
    float* out = (float*)d_out;

    mlp_kernel<<<dim3(SS2, 8), 256>>>(W1, b1, W2, b2);

    cudaFuncSetAttribute(conv_kernel, cudaFuncAttributeMaxDynamicSharedMemorySize, SMEM_BYTES);
    conv_kernel<<<dim3(Ww / TILE, Hh / TILE, Nn), 256, SMEM_BYTES>>>(x, out);
}

// round 6
// speedup vs baseline: 1.0042x; 1.0027x over previous
#include <cuda_runtime.h>
#include <cstdint>

// Problem constants (fixed by setup_inputs)
#define Nn     4
#define Cc     64
#define Hh     192
#define Ww     192
#define OUTC   3
#define Ss     4
#define SS2    16          // s*s
#define CK     576         // C*9
#define WCOLS  48          // s*s*outC
#define HIDDEN 256
#define M2     1728        // KS*KS*C*outC
#define TILE   16
#define HOUT   768
#define WOUT   768

// Dynamic conv weights, rearranged as g_w[k][sp*3+o], k = c*9 + i*3 + j
__device__ float g_w[CK * WCOLS];

// ---------------------------------------------------------------------------
// Stage 1: Pos2Weight MLP. grid = (16 subpixels, 8 m-chunks), block = 256.
// ---------------------------------------------------------------------------
__global__ void mlp_kernel(const float* __restrict__ W1, const float* __restrict__ b1,
                           const float* __restrict__ W2, const float* __restrict__ b2) {
    __shared__ float hidden[HIDDEN];
    const int sp = blockIdx.x;
    const int chunk = blockIdx.y;      // 8 chunks of 216 m-values (8*216 = 1728)
    const int tid = threadIdx.x;

    const float p0 = 0.25f;
    const float p1 = (float)(sp >> 2) * 0.25f;
    const float p2 = (float)(sp & 3) * 0.25f;

    float h = fmaf(p0, W1[tid], fmaf(p1, W1[256 + tid], fmaf(p2, W1[512 + tid], b1[tid])));
    hidden[tid] = fmaxf(h, 0.0f);
    __syncthreads();

    if (tid < 216) {
        const int m = chunk * 216 + tid;
        float sum = b2[m];
        #pragma unroll 8
        for (int j = 0; j < HIDDEN; ++j)
            sum = fmaf(hidden[j], W2[j * M2 + m], sum);
        const int k = m / 3;
        const int o = m - k * 3;
        g_w[k * WCOLS + sp * 3 + o] = sum;
    }
}

// ---------------------------------------------------------------------------
// f32x2 packed-math helpers (FFMA2 only reachable via PTX on sm_103a)
// ---------------------------------------------------------------------------
typedef unsigned long long u64;

__device__ __forceinline__ u64 f2dup(float v) {
    u64 r;
    asm("mov.b64 %0, {%1, %1};" : "=l"(r) : "f"(v));
    return r;
}
__device__ __forceinline__ u64 ffma2(u64 a, u64 b, u64 c) {
    u64 d;
    asm("fma.rn.f32x2 %0, %1, %2, %3;" : "=l"(d) : "l"(a), "l"(b), "l"(c));
    return d;
}
__device__ __forceinline__ void f2unpack(u64 v, float& lo, float& hi) {
    asm("mov.b64 {%0, %1}, %2;" : "=f"(lo), "=f"(hi) : "l"(v));
}

// ---------------------------------------------------------------------------
// Stage 2: fused dynamic conv + pixel shuffle.
// grid = (12, 12, 4) tiles; block = 256 threads.
// smem: weights 27648 f + input halo tile 64*18*18 = 20736 f  (193,536 B)
// Thread = 2x2 pixel block x 12 output columns (one si group), 24 f32x2 accs.
// ---------------------------------------------------------------------------
#define SW_FLOATS (CK * WCOLS)          // 27648
#define SX_FLOATS (Cc * 18 * 18)        // 20736
#define SMEM_BYTES ((SW_FLOATS + SX_FLOATS) * 4)

__global__ void __launch_bounds__(256, 1)
conv_kernel(const float* __restrict__ in, float* __restrict__ out) {
    extern __shared__ float smem[];
    float* sw = smem;                   // [576][48]
    float* sx = smem + SW_FLOATS;       // [64][18][18]
    float* stage = sx;                  // reused after compute: [12][16][64]

    const int tw = blockIdx.x, th = blockIdx.y, n = blockIdx.z;
    const int tid = threadIdx.x;

    // --- load weights (float4, coalesced) ---
    {
        const float4* gw4 = (const float4*)g_w;
        float4* sw4 = (float4*)sw;
        #pragma unroll 4
        for (int i = tid; i < SW_FLOATS / 4; i += 256) sw4[i] = gw4[i];
    }

    // --- load 18x18x64 halo tile with zero padding ---
    {
        const int gh0 = th * TILE - 1, gw0 = tw * TILE - 1;
        const float* inb = in + (size_t)n * Cc * Hh * Ww;
        for (int i = tid; i < SX_FLOATS; i += 256) {
            int c = i / 324, r = i - c * 324;
            int lh = r / 18, lw = r - lh * 18;
            int gh = gh0 + lh, gw = gw0 + lw;
            float v = 0.0f;
            if ((unsigned)gh < (unsigned)Hh && (unsigned)gw < (unsigned)Ww)
                v = inb[(c * Hh + gh) * Ww + gw];
            sx[i] = v;
        }
    }
    __syncthreads();

    const int og = tid & 3;             // output-column group: cols [og*12, og*12+12) -> si == og
    const int pg = tid >> 2;            // pixel group: 8x8 grid of 2x2 blocks
    const int h0l = (pg >> 3) * 2;      // local pixel row of 2x2 block
    const int w0l = (pg & 7) * 2;

    u64 acc[2][2][6];                   // [pixel r][pixel q][col pair]
    #pragma unroll
    for (int r = 0; r < 2; ++r)
        #pragma unroll
        for (int q = 0; q < 2; ++q)
            #pragma unroll
            for (int cp = 0; cp < 6; ++cp) acc[r][q][cp] = 0ull;

    #pragma unroll 1
    for (int c = 0; c < Cc; ++c) {
        // 4x4 input patch for this channel, broadcast-packed into f32x2 regs
        const float* xp = sx + c * 324 + h0l * 18 + w0l;
        u64 P[4][4];
        #pragma unroll
        for (int rr = 0; rr < 4; ++rr)
            #pragma unroll
            for (int qq = 0; qq < 4; ++qq)
                P[rr][qq] = f2dup(xp[rr * 18 + qq]);

        const float* wc = sw + c * 9 * WCOLS + og * 12;
        #pragma unroll
        for (int i = 0; i < 3; ++i) {
            #pragma unroll
            for (int j = 0; j < 3; ++j) {
                const ulonglong2* wv = (const ulonglong2*)(wc + (i * 3 + j) * WCOLS);
                ulonglong2 a = wv[0], b = wv[1], d = wv[2];
                u64 Wp[6] = {a.x, a.y, b.x, b.y, d.x, d.y};
                #pragma unroll
                for (int r = 0; r < 2; ++r)
                    #pragma unroll
                    for (int q = 0; q < 2; ++q)
                        #pragma unroll
                        for (int cp = 0; cp < 6; ++cp)
                            acc[r][q][cp] = ffma2(P[i + r][j + q], Wp[cp], acc[r][q][cp]);
            }
        }
    }

    __syncthreads();   // sx no longer needed; reuse as output staging

    // --- scatter accumulators into pixel-shuffled staging layout ---
    // stage[((o*4+si)*16 + hl)*64 + wl*4 + sj]
    #pragma unroll
    for (int r = 0; r < 2; ++r) {
        #pragma unroll
        for (int q = 0; q < 2; ++q) {
            const int hl = h0l + r, wl = w0l + q;
            #pragma unroll
            for (int cp = 0; cp < 6; ++cp) {
                float lo, hi;
                f2unpack(acc[r][q][cp], lo, hi);
                #pragma unroll
                for (int e = 0; e < 2; ++e) {
                    const int col = og * 12 + 2 * cp + e;   // = sp*3 + o
                    const int sp = col / 3;
                    const int o  = col - sp * 3;
                    const int si = sp >> 2;                 // == og
                    const int sj = sp & 3;
                    stage[(((o * 4 + si) * 16) + hl) * 64 + wl * 4 + sj] = (e == 0) ? lo : hi;
                }
            }
        }
    }
    __syncthreads();

    // --- coalesced float4 stores: each (o, hl, si) row is 64 contiguous floats ---
    {
        float* outb = out + (size_t)n * OUTC * HOUT * WOUT;
        const float4* st4 = (const float4*)stage;
        #pragma unroll
        for (int v = tid; v < (12 * 16 * 64) / 4; v += 256) {
            const int flat = v * 4;
            const int seg = flat >> 6;          // (o*4+si)*16 + hl
            const int cc = flat & 63;
            const int o = seg >> 6;
            const int rem = seg & 63;
            const int si = rem >> 4;
            const int hl = rem & 15;
            const int gh = (th * TILE + hl) * Ss + si;
            const int gw = tw * 64 + cc;
            *(float4*)(outb + ((size_t)o * HOUT + gh) * WOUT + gw) = st4[v];
        }
    }
}

// ---------------------------------------------------------------------------
extern "C" void kernel_launch(void* const* d_in, const int* in_sizes, int n_in,
                              void* d_out, int out_size) {
    const float* x  = (const float*)d_in[0];
    const float* W1 = (const float*)d_in[1];
    const float* b1 = (const float*)d_in[2];
    const float* W2 = (const float*)d_in[3];
    const float* b2 = (const float*)d_in[4];
    float* out = (float*)d_out;

    mlp_kernel<<<dim3(SS2, 8), 256>>>(W1, b1, W2, b2);

    cudaFuncSetAttribute(conv_kernel, cudaFuncAttributeMaxDynamicSharedMemorySize, SMEM_BYTES);
    conv_kernel<<<dim3(Ww / TILE, Hh / TILE, Nn), 256, SMEM_BYTES>>>(x, out);
}